// round 1
// baseline (speedup 1.0000x reference)
#include <cuda_runtime.h>
#include <math.h>

// Problem constants (fixed by the reference)
#define BB 16384
#define KK 50
#define HH 64
#define REGC 0.01f

// Scratch for loss accumulation: [0]=sum sq err, [1]=sum ||ie||, [2]=sum ||ue||
__device__ float g_scratch[3];

__global__ void zero_scratch_kernel() {
    if (threadIdx.x < 3) g_scratch[threadIdx.x] = 0.0f;
}

__global__ __launch_bounds__(128) void mf_main_kernel(
    const float* __restrict__ uw,      // [100000,64]
    const float* __restrict__ iw,      // [1000000,64]
    const float* __restrict__ ub,      // [100000,1]
    const float* __restrict__ ib,      // [1000000,1]
    const float* __restrict__ bias,    // [1]
    const float* __restrict__ target,  // [B,K]
    const int*   __restrict__ user,    // [B]
    const int*   __restrict__ item,    // [B,K]
    float* __restrict__ out)           // [B*K + 1]
{
    __shared__ float ue_s[HH];
    __shared__ float tgt_s[KK];
    __shared__ int   itm_s[KK];
    __shared__ float red_s[2];
    __shared__ float ms_s[8], ns_s[8];

    const int b    = blockIdx.x;
    const int tid  = threadIdx.x;
    const int warp = tid >> 5;
    const int lane = tid & 31;
    const int half = (lane >> 4) & 1;   // 0 or 1: which half-warp
    const int hl   = lane & 15;         // lane within half-warp

    const int u = user[b];

    // Stage indices + targets for this b (coalesced)
    if (tid < KK) {
        itm_s[tid] = item[b * KK + tid];
        tgt_s[tid] = target[b * KK + tid];
    }

    // Load user embedding row (+scalar user bias broadcast) into shared
    float uval = 0.0f;
    if (tid < HH) {
        uval = uw[(size_t)u * HH + tid] + ub[u];
        ue_s[tid] = uval;
    }
    // ||ue||^2 : warps 0,1 hold the 64 values; full-warp butterfly reduce
    float usq = uval * uval;
    #pragma unroll
    for (int m = 16; m >= 1; m >>= 1)
        usq += __shfl_xor_sync(0xffffffffu, usq, m);
    if (warp < 2 && lane == 0) red_s[warp] = usq;
    __syncthreads();

    float ue_norm = 0.0f;
    if (tid == 0) ue_norm = sqrtf(red_s[0] + red_s[1]);

    const float gbias = bias[0];
    const float4* __restrict__ iw4 = (const float4*)iw;
    const float4  u4 = ((const float4*)ue_s)[hl];   // ue chunk for this lane

    float macc = 0.0f;   // sum (pred-target)^2 (on hl==0 lanes)
    float nacc = 0.0f;   // sum ||ie||         (on hl==0 lanes)

    // 4 warps x 2 half-warps = 8 items per round; ceil(50/8) = 7 rounds.
    #pragma unroll 1
    for (int r = 0; r < 7; ++r) {
        const int k   = r * 8 + warp * 2 + half;
        const bool act = (k < KK);
        const int idx = act ? itm_s[k] : 0;

        const float ibv = ib[idx];                        // broadcast within half-warp
        const float4 w  = iw4[(size_t)idx * (HH / 4) + hl]; // coalesced 256B row per half-warp

        float4 e;
        e.x = w.x + ibv; e.y = w.y + ibv; e.z = w.z + ibv; e.w = w.w + ibv;

        float dot = e.x * u4.x + e.y * u4.y + e.z * u4.z + e.w * u4.w;
        float sq  = e.x * e.x  + e.y * e.y  + e.z * e.z  + e.w * e.w;

        #pragma unroll
        for (int m = 8; m >= 1; m >>= 1) {
            dot += __shfl_xor_sync(0xffffffffu, dot, m);
            sq  += __shfl_xor_sync(0xffffffffu, sq,  m);
        }

        if (act && hl == 0) {
            const float pred = dot + gbias;
            out[(size_t)b * KK + k] = pred;
            const float d = pred - tgt_s[k];
            macc += d * d;
            nacc += sqrtf(sq);
        }
    }

    // Block-level reduce of the 8 half-warp leaders, then 3 atomics per block.
    if (hl == 0) { ms_s[warp * 2 + half] = macc; ns_s[warp * 2 + half] = nacc; }
    __syncthreads();
    if (tid == 0) {
        float m = 0.0f, n = 0.0f;
        #pragma unroll
        for (int i = 0; i < 8; ++i) { m += ms_s[i]; n += ns_s[i]; }
        atomicAdd(&g_scratch[0], m);
        atomicAdd(&g_scratch[1], n);
        atomicAdd(&g_scratch[2], ue_norm);
    }
}

__global__ void finalize_kernel(float* __restrict__ out) {
    const float inv_bk = 1.0f / (float)((size_t)BB * KK);
    const float loss = g_scratch[0] * inv_bk
                     + REGC * (g_scratch[2] * (1.0f / (float)BB))
                     + REGC * (g_scratch[1] * inv_bk);
    out[(size_t)BB * KK] = loss;
}

extern "C" void kernel_launch(void* const* d_in, const int* in_sizes, int n_in,
                              void* d_out, int out_size) {
    const float* uw     = (const float*)d_in[0];
    const float* iw     = (const float*)d_in[1];
    const float* ub     = (const float*)d_in[2];
    const float* ib     = (const float*)d_in[3];
    const float* bias   = (const float*)d_in[4];
    const float* target = (const float*)d_in[5];
    const int*   user   = (const int*)d_in[6];
    const int*   item   = (const int*)d_in[7];
    float* out = (float*)d_out;

    zero_scratch_kernel<<<1, 32>>>();
    mf_main_kernel<<<BB, 128>>>(uw, iw, ub, ib, bias, target, user, item, out);
    finalize_kernel<<<1, 1>>>(out);
}

// round 2
// speedup vs baseline: 1.0876x; 1.0876x over previous
#include <cuda_runtime.h>
#include <math.h>

// Problem constants (fixed by the reference)
#define BB 16384
#define KK 50
#define HH 64
#define REGC 0.01f
#define RPH 7   // items per half-warp (ceil(50/8))

// Scratch for loss accumulation: [0]=sum sq err, [1]=sum ||ie||, [2]=sum ||ue||
// Statically zero-initialized; finalize_kernel re-zeroes after use, so the
// "starts at zero" invariant holds for every kernel_launch call / graph replay.
__device__ float g_scratch[3];

__global__ __launch_bounds__(128) void mf_main_kernel(
    const float* __restrict__ uw,      // [100000,64]
    const float* __restrict__ iw,      // [1000000,64]
    const float* __restrict__ ub,      // [100000,1]
    const float* __restrict__ ib,      // [1000000,1]
    const float* __restrict__ bias,    // [1]
    const float* __restrict__ target,  // [B,K]
    const int*   __restrict__ user,    // [B]
    const int*   __restrict__ item,    // [B,K]
    float* __restrict__ out)           // [B*K + 1]
{
    __shared__ float ue_s[HH];
    __shared__ float tgt_s[KK];
    __shared__ int   itm_s[KK];
    __shared__ float red_s[2];
    __shared__ float ms_s[8], ns_s[8];

    const int b    = blockIdx.x;
    const int tid  = threadIdx.x;
    const int warp = tid >> 5;
    const int lane = tid & 31;
    const int half = (lane >> 4) & 1;   // which half-warp
    const int hl   = lane & 15;         // lane within half-warp
    const int hw   = warp * 2 + half;   // half-warp id 0..7

    const int u = user[b];

    // Stage indices + targets for this b (coalesced)
    if (tid < KK) {
        itm_s[tid] = item[b * KK + tid];
        tgt_s[tid] = target[b * KK + tid];
    }

    // Load user embedding row (+scalar user bias broadcast) into shared
    float uval = 0.0f;
    if (tid < HH) {
        uval = uw[(size_t)u * HH + tid] + ub[u];
        ue_s[tid] = uval;
    }
    float usq = uval * uval;
    #pragma unroll
    for (int m = 16; m >= 1; m >>= 1)
        usq += __shfl_xor_sync(0xffffffffu, usq, m);
    if (warp < 2 && lane == 0) red_s[warp] = usq;
    __syncthreads();

    const float gbias = bias[0];
    const float4* __restrict__ iw4 = (const float4*)iw;
    const float4  u4 = ((const float4*)ue_s)[hl];

    // ---- Phase 1: gather all item indices for this half-warp ----
    int  idxs[RPH];
    bool act[RPH];
    #pragma unroll
    for (int r = 0; r < RPH; ++r) {
        const int k = r * 8 + hw;
        act[r]  = (k < KK);
        idxs[r] = act[r] ? itm_s[k] : 0;
    }

    // ---- Phase 2: issue ALL row + bias gathers (independent, front-batched) ----
    float4 w[RPH];
    float  ibv[RPH];
    #pragma unroll
    for (int r = 0; r < RPH; ++r) {
        if (act[r]) {
            w[r]   = iw4[(size_t)idxs[r] * (HH / 4) + hl];  // coalesced 256B row / half-warp
            ibv[r] = ib[idxs[r]];
        } else {
            w[r]   = make_float4(0.f, 0.f, 0.f, 0.f);
            ibv[r] = 0.f;
        }
    }

    // ---- Phase 3: reduce each item ----
    float macc = 0.0f;   // sum (pred-target)^2 (hl==0 lanes)
    float nacc = 0.0f;   // sum ||ie||         (hl==0 lanes)

    #pragma unroll
    for (int r = 0; r < RPH; ++r) {
        float4 e;
        e.x = w[r].x + ibv[r]; e.y = w[r].y + ibv[r];
        e.z = w[r].z + ibv[r]; e.w = w[r].w + ibv[r];

        float dot = e.x * u4.x + e.y * u4.y + e.z * u4.z + e.w * u4.w;
        float sq  = e.x * e.x  + e.y * e.y  + e.z * e.z  + e.w * e.w;

        #pragma unroll
        for (int m = 8; m >= 1; m >>= 1) {
            dot += __shfl_xor_sync(0xffffffffu, dot, m);
            sq  += __shfl_xor_sync(0xffffffffu, sq,  m);
        }

        if (act[r] && hl == 0) {
            const int k = r * 8 + hw;
            const float pred = dot + gbias;
            out[(size_t)b * KK + k] = pred;
            const float d = pred - tgt_s[k];
            macc += d * d;
            nacc += sqrtf(sq);
        }
    }

    // Block-level reduce of the 8 half-warp leaders, then 3 atomics per block.
    if (hl == 0) { ms_s[hw] = macc; ns_s[hw] = nacc; }
    __syncthreads();
    if (tid == 0) {
        float m = 0.0f, n = 0.0f;
        #pragma unroll
        for (int i = 0; i < 8; ++i) { m += ms_s[i]; n += ns_s[i]; }
        atomicAdd(&g_scratch[0], m);
        atomicAdd(&g_scratch[1], n);
        atomicAdd(&g_scratch[2], sqrtf(red_s[0] + red_s[1]));
    }
}

__global__ void finalize_kernel(float* __restrict__ out) {
    const float inv_bk = 1.0f / (float)((size_t)BB * KK);
    const float loss = g_scratch[0] * inv_bk
                     + REGC * (g_scratch[2] * (1.0f / (float)BB))
                     + REGC * (g_scratch[1] * inv_bk);
    out[(size_t)BB * KK] = loss;
    // Reset for the next call / replay (maintains the zero-start invariant).
    g_scratch[0] = 0.0f; g_scratch[1] = 0.0f; g_scratch[2] = 0.0f;
}

extern "C" void kernel_launch(void* const* d_in, const int* in_sizes, int n_in,
                              void* d_out, int out_size) {
    const float* uw     = (const float*)d_in[0];
    const float* iw     = (const float*)d_in[1];
    const float* ub     = (const float*)d_in[2];
    const float* ib     = (const float*)d_in[3];
    const float* bias   = (const float*)d_in[4];
    const float* target = (const float*)d_in[5];
    const int*   user   = (const int*)d_in[6];
    const int*   item   = (const int*)d_in[7];
    float* out = (float*)d_out;

    mf_main_kernel<<<BB, 128>>>(uw, iw, ub, ib, bias, target, user, item, out);
    finalize_kernel<<<1, 1>>>(out);
}